// round 15
// baseline (speedup 1.0000x reference)
#include <cuda_runtime.h>
#include <cuda_fp16.h>
#include <cstdint>

// Problem constants (fixed by the dataset)
constexpr int NTOK = 4096;      // B*S = 4*1024
constexpr int E    = 512;
constexpr int C    = 512;
constexpr int H    = 1024;
constexpr int V    = 32000;
constexpr float EPS = 1e-5f;

constexpr int W_ELEMS  = 3 * 2 * H * H;
constexpr int OW_ELEMS = V * C;
constexpr int W4  = W_ELEMS / 4;
constexpr int OW4 = OW_ELEMS / 4;

// Tiling: 128x256x64, 256 threads (8 warps, 2Mx4N), warp tile 64x64.
constexpr int BM = 128, BN = 256, BK = 64;
constexpr int A_T     = BM * BK * 2;              // 16384 B
constexpr int B_T     = BN * BK * 2;              // 32768 B
constexpr int STAGES  = 3;
constexpr int G_STAGE = A_T + B_T;                // 49152
constexpr int G_SMEM  = STAGES * G_STAGE;         // 147456

// Logits persistent kernel geometry
constexpr int L_TN    = V / BN;                   // 125 N-tiles
constexpr int L_TOTAL = L_TN * (NTOK / BM);       // 4000 tiles
constexpr int L_GRID  = 148;                      // one CTA per SM
constexpr int L_NCH   = C / BK;                   // 8 chunks per tile

// Scratch (allocation-free rule: __device__ globals)
__device__ float g_hbuf[NTOK * H];                // fp32 residual state [ctx|tok]
__device__ __half g_h2h[NTOK * H];                // fp16 FNN block output
__device__ __half g_xh[NTOK * H];                 // x fp16 (GEMM-1 in; xh[:,C:] = logits A)
__device__ __half g_yh[NTOK * H];                 // GEMM-2 input fp16
__device__ __half g_wh[W_ELEMS];                  // FNN weights fp16
__device__ __half g_owh[OW_ELEMS];                // out_W fp16

// ---------------------------------------------------------------------------
// PTX helpers
// ---------------------------------------------------------------------------
__device__ __forceinline__ uint32_t cvta_smem(const void* p) {
    uint32_t a;
    asm("{\n\t.reg .u64 t;\n\tcvta.to.shared.u64 t, %1;\n\tcvt.u32.u64 %0, t;\n\t}"
        : "=r"(a) : "l"(p));
    return a;
}
__device__ __forceinline__ uint32_t swz(uint32_t o) { return o ^ ((o >> 3) & 0x70); }

__device__ __forceinline__ void cp16(uint32_t dst, const void* src) {
    asm volatile("cp.async.cg.shared.global [%0], [%1], 16;" :: "r"(dst), "l"(src));
}
__device__ __forceinline__ void cp_commit() {
    asm volatile("cp.async.commit_group;" ::: "memory");
}

__device__ __forceinline__ void ldsm4(uint32_t* r, uint32_t addr) {
    asm volatile("ldmatrix.sync.aligned.m8n8.x4.shared.b16 {%0,%1,%2,%3}, [%4];"
                 : "=r"(r[0]), "=r"(r[1]), "=r"(r[2]), "=r"(r[3]) : "r"(addr));
}

__device__ __forceinline__ void mma16816h(float* d, const uint32_t* a,
                                          uint32_t b0, uint32_t b1) {
    asm("mma.sync.aligned.m16n8k16.row.col.f32.f16.f16.f32 "
        "{%0,%1,%2,%3}, {%4,%5,%6,%7}, {%8,%9}, {%0,%1,%2,%3};"
        : "+f"(d[0]), "+f"(d[1]), "+f"(d[2]), "+f"(d[3])
        : "r"(a[0]), "r"(a[1]), "r"(a[2]), "r"(a[3]), "r"(b0), "r"(b1));
}

__device__ __forceinline__ uint32_t pack_h2(float a, float b) {
    return (uint32_t)__half_as_ushort(__float2half_rn(a)) |
           ((uint32_t)__half_as_ushort(__float2half_rn(b)) << 16);
}

// ---------------------------------------------------------------------------
// fp32 -> fp16: both weight arrays in ONE launch
// ---------------------------------------------------------------------------
__global__ void __launch_bounds__(256) conv_weights(
    const float4* __restrict__ Wb, const float4* __restrict__ oW,
    uint2* __restrict__ wh, uint2* __restrict__ owh)
{
    const int i = blockIdx.x * 256 + threadIdx.x;
    if (i < W4) {
        const float4 x = Wb[i];
        wh[i] = make_uint2(pack_h2(x.x, x.y), pack_h2(x.z, x.w));
    } else if (i < W4 + OW4) {
        const float4 x = oW[i - W4];
        owh[i - W4] = make_uint2(pack_h2(x.x, x.y), pack_h2(x.z, x.w));
    }
}

// ---------------------------------------------------------------------------
// 128-thread-group reduction (two groups per 256-thread block)
// ---------------------------------------------------------------------------
__device__ __forceinline__ void group_reduce_2(float& s, float& s2,
                                               int grp, int wig) {
    #pragma unroll
    for (int o = 16; o > 0; o >>= 1) {
        s  += __shfl_xor_sync(0xFFFFFFFFu, s,  o);
        s2 += __shfl_xor_sync(0xFFFFFFFFu, s2, o);
    }
    __shared__ float red[2][8];
    int lid = threadIdx.x & 31;
    if (lid == 0) { red[grp][wig] = s; red[grp][4 + wig] = s2; }
    __syncthreads();
    s  = red[grp][0] + red[grp][1] + red[grp][2] + red[grp][3];
    s2 = red[grp][4] + red[grp][5] + red[grp][6] + red[grp][7];
}

// ---------------------------------------------------------------------------
// Embedding gather + LN -> hbuf fp32 [0|tok] and x fp16 (full row)
// ---------------------------------------------------------------------------
__global__ void __launch_bounds__(128) embed_ln_kernel(
    const int* __restrict__ ids, const float* __restrict__ table,
    const float* __restrict__ g, const float* __restrict__ b)
{
    const int tok = blockIdx.x;
    const int tid = threadIdx.x;
    const long id = ids[tok];

    float4 x = reinterpret_cast<const float4*>(table + id * (long)E)[tid];
    float s  = x.x + x.y + x.z + x.w;
    float s2 = x.x * x.x + x.y * x.y + x.z * x.z + x.w * x.w;
    #pragma unroll
    for (int o = 16; o > 0; o >>= 1) {
        s  += __shfl_xor_sync(0xFFFFFFFFu, s,  o);
        s2 += __shfl_xor_sync(0xFFFFFFFFu, s2, o);
    }
    __shared__ float red[8];
    int wid = tid >> 5, lid = tid & 31;
    if (lid == 0) { red[wid] = s; red[4 + wid] = s2; }
    __syncthreads();
    s  = red[0] + red[1] + red[2] + red[3];
    s2 = red[4] + red[5] + red[6] + red[7];

    const float mean = s * (1.0f / E);
    const float var  = s2 * (1.0f / E) - mean * mean;
    const float rstd = rsqrtf(var + EPS);

    float4 gg = reinterpret_cast<const float4*>(g)[tid];
    float4 bb = reinterpret_cast<const float4*>(b)[tid];
    float4 y;
    y.x = (x.x - mean) * rstd * gg.x + bb.x;
    y.y = (x.y - mean) * rstd * gg.y + bb.y;
    y.z = (x.z - mean) * rstd * gg.z + bb.z;
    y.w = (x.w - mean) * rstd * gg.w + bb.w;

    const long rbase = (long)tok * H;
    float* row = g_hbuf + rbase;
    reinterpret_cast<float4*>(row + C)[tid] = y;
    reinterpret_cast<float4*>(row)[tid] = make_float4(0.f, 0.f, 0.f, 0.f);

    reinterpret_cast<uint2*>(g_xh + rbase + C)[tid] =
        make_uint2(pack_h2(y.x, y.y), pack_h2(y.z, y.w));
    reinterpret_cast<uint2*>(g_xh + rbase)[tid] = make_uint2(0, 0);
}

// ---------------------------------------------------------------------------
// Residual + LN, BOTH halves in one 256-thread block (grp 0 = ctx, 1 = tok).
// Reads h2 in fp16; writes hbuf fp32 and x fp16.
// ---------------------------------------------------------------------------
__global__ void __launch_bounds__(256) resid_ln_kernel(
    const float* __restrict__ cg, const float* __restrict__ cb,
    const float* __restrict__ tg, const float* __restrict__ tb)
{
    const int tok = blockIdx.x;
    const int grp = threadIdx.x >> 7;
    const int t   = threadIdx.x & 127;
    const int wig = (threadIdx.x >> 5) & 3;
    const float* g  = grp ? tg : cg;
    const float* bp = grp ? tb : cb;

    const long base = (long)tok * H + grp * C;
    float4 a = reinterpret_cast<const float4*>(g_hbuf + base)[t];
    uint2 hp = reinterpret_cast<const uint2*>(g_h2h + base)[t];
    float2 h0 = __half22float2(*reinterpret_cast<__half2*>(&hp.x));
    float2 h1 = __half22float2(*reinterpret_cast<__half2*>(&hp.y));
    float4 x;
    x.x = a.x + h0.x; x.y = a.y + h0.y; x.z = a.z + h1.x; x.w = a.w + h1.y;

    float s  = x.x + x.y + x.z + x.w;
    float s2 = x.x * x.x + x.y * x.y + x.z * x.z + x.w * x.w;
    group_reduce_2(s, s2, grp, wig);

    const float mean = s * (1.0f / C);
    const float var  = s2 * (1.0f / C) - mean * mean;
    const float rstd = rsqrtf(var + EPS);

    float4 gg = reinterpret_cast<const float4*>(g)[t];
    float4 bb = reinterpret_cast<const float4*>(bp)[t];
    float4 y;
    y.x = (x.x - mean) * rstd * gg.x + bb.x;
    y.y = (x.y - mean) * rstd * gg.y + bb.y;
    y.z = (x.z - mean) * rstd * gg.z + bb.z;
    y.w = (x.w - mean) * rstd * gg.w + bb.w;
    reinterpret_cast<float4*>(g_hbuf + base)[t] = y;

    reinterpret_cast<uint2*>(g_xh + base)[t] =
        make_uint2(pack_h2(y.x, y.y), pack_h2(y.z, y.w));
}

// ---------------------------------------------------------------------------
// FNN GEMM: 128x256 tile, warp 64x64, single launch wave (R13/R14 config).
// ---------------------------------------------------------------------------
template <bool RELU, bool OUT16>
__global__ void __launch_bounds__(256, 1) gemm_f16(
    const __half* __restrict__ A, int lda,
    const __half* __restrict__ B, int ldb,
    const float* __restrict__ bias,
    float* __restrict__ Cf, __half* __restrict__ Ch,
    int ldc, int K)
{
    extern __shared__ char smem[];
    const uint32_t sb = cvta_smem(smem);
    const int tid = threadIdx.x;
    const int w   = tid >> 5;
    const int l   = tid & 31;
    const int wm  = (w >> 2) * 64;
    const int wn  = (w & 3) * 64;
    const long m0 = (long)blockIdx.y * BM;
    const long n0 = (long)blockIdx.x * BN;

    const int lrow  = ((l >> 3) & 1) * 8 + (l & 7);
    const int lkseg = ((l >> 4) & 1) * 16;

    const int NC = K >> 6;

    const int ldr  = tid >> 3;
    const int ldc8 = (tid & 7) * 8;
    const uint32_t lso = (uint32_t)((tid & 7) * 16);

    auto load_part = [&](int c, uint32_t sbase, int it) {
        const int k0 = c << 6;
        const int r = it * 32 + ldr;
        if (r < BM) {
            cp16(sbase + swz((uint32_t)(r * 128) + lso),
                 A + (m0 + r) * (long)lda + k0 + ldc8);
        } else {
            cp16(sbase + A_T + swz((uint32_t)((r - BM) * 128) + lso),
                 B + (n0 + r - BM) * (long)ldb + k0 + ldc8);
        }
    };
    auto load_chunk = [&](int c, int stage) {
        const uint32_t sbase = sb + (uint32_t)stage * G_STAGE;
        #pragma unroll
        for (int it = 0; it < 12; ++it) load_part(c, sbase, it);
    };

    float acc[4][8][4];
    #pragma unroll
    for (int i = 0; i < 4; ++i)
        #pragma unroll
        for (int j = 0; j < 8; ++j)
            #pragma unroll
            for (int q = 0; q < 4; ++q) acc[i][j][q] = 0.0f;

    uint32_t Af[4][4], Bf[4][4];

    auto ld_frag = [&](uint32_t sbase, int ks) {
        const int kb = ks * 32 + lkseg;
        #pragma unroll
        for (int mf = 0; mf < 4; ++mf) {
            const uint32_t off = swz((uint32_t)((wm + mf * 16 + lrow) * 128 + kb));
            ldsm4(Af[mf], sbase + off);
        }
        #pragma unroll
        for (int nf2 = 0; nf2 < 4; ++nf2) {
            const uint32_t off = swz((uint32_t)((wn + nf2 * 16 + lrow) * 128 + kb));
            ldsm4(Bf[nf2], sbase + A_T + off);
        }
    };
    auto mma_all = [&]() {
        #pragma unroll
        for (int mf = 0; mf < 4; ++mf)
            #pragma unroll
            for (int nf = 0; nf < 8; ++nf) {
                const int p = nf >> 1, q = nf & 1;
                mma16816h(acc[mf][nf], Af[mf], Bf[p][q], Bf[p][q + 2]);
            }
    };

    load_chunk(0, 0); cp_commit();
    if (NC > 1) { load_chunk(1, 1); cp_commit(); }

    for (int c = 0; c < NC; ++c) {
        if (c + 1 < NC) asm volatile("cp.async.wait_group 1;" ::: "memory");
        else            asm volatile("cp.async.wait_group 0;" ::: "memory");
        __syncthreads();

        const uint32_t sbase = sb + (uint32_t)(c % STAGES) * G_STAGE;
        const int cn = c + 2;
        const uint32_t nbase = sb + (uint32_t)(cn % STAGES) * G_STAGE;
        const bool has_next = cn < NC;

        #pragma unroll
        for (int ks = 0; ks < 4; ++ks) {
            ld_frag(sbase, ks);
            if (has_next) {
                #pragma unroll
                for (int p = 0; p < 3; ++p) load_part(cn, nbase, ks * 3 + p);
            }
            mma_all();
        }
        if (has_next) cp_commit();
    }

    const int tig = l & 3, grp = l >> 2;
    #pragma unroll
    for (int nf = 0; nf < 8; ++nf) {
        const long col = n0 + wn + nf * 8 + 2 * tig;
        const float b0 = bias[col], b1 = bias[col + 1];
        #pragma unroll
        for (int mf = 0; mf < 4; ++mf) {
            const long r0 = m0 + wm + mf * 16 + grp;
            float v00 = acc[mf][nf][0] + b0, v01 = acc[mf][nf][1] + b1;
            float v10 = acc[mf][nf][2] + b0, v11 = acc[mf][nf][3] + b1;
            if (RELU) {
                v00 = fmaxf(v00, 0.f); v01 = fmaxf(v01, 0.f);
                v10 = fmaxf(v10, 0.f); v11 = fmaxf(v11, 0.f);
            }
            if (OUT16) {
                *reinterpret_cast<uint32_t*>(Ch + r0 * (long)ldc + col) = pack_h2(v00, v01);
                *reinterpret_cast<uint32_t*>(Ch + (r0 + 8) * (long)ldc + col) = pack_h2(v10, v11);
            } else {
                *reinterpret_cast<float2*>(Cf + r0 * (long)ldc + col) = make_float2(v00, v01);
                *reinterpret_cast<float2*>(Cf + (r0 + 8) * (long)ldc + col) = make_float2(v10, v11);
            }
        }
    }
}

// ---------------------------------------------------------------------------
// Logits GEMM, PERSISTENT: grid = 148, each CTA walks tiles bid + k*148.
// The 3-stage cp.async ring rolls across tile boundaries (epilogue is
// register-only, so next tile's chunk loads overlap it). Ramp paid once
// per CTA instead of once per tile generation (27x).
// ---------------------------------------------------------------------------
__global__ void __launch_bounds__(256, 1) gemm_logits_persist(
    const __half* __restrict__ A, int lda,
    const __half* __restrict__ B, int ldb,
    const float* __restrict__ bias,
    float* __restrict__ Cf, int ldc)
{
    extern __shared__ char smem[];
    const uint32_t sb = cvta_smem(smem);
    const int tid = threadIdx.x;
    const int w   = tid >> 5;
    const int l   = tid & 31;
    const int wm  = (w >> 2) * 64;
    const int wn  = (w & 3) * 64;

    const int lrow  = ((l >> 3) & 1) * 8 + (l & 7);
    const int lkseg = ((l >> 4) & 1) * 16;

    const int ldr  = tid >> 3;
    const int ldc8 = (tid & 7) * 8;
    const uint32_t lso = (uint32_t)((tid & 7) * 16);

    const int bid = blockIdx.x;
    const int G   = gridDim.x;
    const int tcount = (L_TOTAL - bid + G - 1) / G;   // tiles for this CTA
    if (tcount <= 0) return;
    const int QT = tcount * L_NCH;                    // total chunks

    auto tile_mn = [&](int t, long& m0, long& n0) {
        const int mi = t / L_TN;
        const int ni = t - mi * L_TN;
        m0 = (long)mi * BM;
        n0 = (long)ni * BN;
    };

    auto load_part = [&](long m0, long n0, int k0, uint32_t sbase, int it) {
        const int r = it * 32 + ldr;
        if (r < BM) {
            cp16(sbase + swz((uint32_t)(r * 128) + lso),
                 A + (m0 + r) * (long)lda + k0 + ldc8);
        } else {
            cp16(sbase + A_T + swz((uint32_t)((r - BM) * 128) + lso),
                 B + (n0 + r - BM) * (long)ldb + k0 + ldc8);
        }
    };

    float acc[4][8][4];
    #pragma unroll
    for (int i = 0; i < 4; ++i)
        #pragma unroll
        for (int j = 0; j < 8; ++j)
            #pragma unroll
            for (int q = 0; q < 4; ++q) acc[i][j][q] = 0.0f;

    uint32_t Af[4][4], Bf[4][4];

    auto ld_frag = [&](uint32_t sbase, int ks) {
        const int kb = ks * 32 + lkseg;
        #pragma unroll
        for (int mf = 0; mf < 4; ++mf) {
            const uint32_t off = swz((uint32_t)((wm + mf * 16 + lrow) * 128 + kb));
            ldsm4(Af[mf], sbase + off);
        }
        #pragma unroll
        for (int nf2 = 0; nf2 < 4; ++nf2) {
            const uint32_t off = swz((uint32_t)((wn + nf2 * 16 + lrow) * 128 + kb));
            ldsm4(Bf[nf2], sbase + A_T + off);
        }
    };
    auto mma_all = [&]() {
        #pragma unroll
        for (int mf = 0; mf < 4; ++mf)
            #pragma unroll
            for (int nf = 0; nf < 8; ++nf) {
                const int p = nf >> 1, q = nf & 1;
                mma16816h(acc[mf][nf], Af[mf], Bf[p][q], Bf[p][q + 2]);
            }
    };

    long km0, kn0;                 // current compute tile coords
    tile_mn(bid, km0, kn0);

    // prologue: chunks q=0,1 (both in first tile; L_NCH=8 > 2)
    {
        #pragma unroll
        for (int it = 0; it < 12; ++it) load_part(km0, kn0, 0, sb, it);
        cp_commit();
        #pragma unroll
        for (int it = 0; it < 12; ++it) load_part(km0, kn0, 64, sb + G_STAGE, it);
        cp_commit();
    }

    const int tig = l & 3, grpl = l >> 2;
    int q = 0;
    for (int k = 0; k < tcount; ++k) {
        long k1m0 = 0, k1n0 = 0;
        if (k + 1 < tcount) tile_mn(bid + (k + 1) * G, k1m0, k1n0);

        for (int c = 0; c < L_NCH; ++c, ++q) {
            if (q + 1 < QT) asm volatile("cp.async.wait_group 1;" ::: "memory");
            else            asm volatile("cp.async.wait_group 0;" ::: "memory");
            __syncthreads();

            const uint32_t sbase = sb + (uint32_t)(q % STAGES) * G_STAGE;
            const bool has_next = (q + 2) < QT;
            const int c2 = c + 2;
            const long pm0 = (c2 < L_NCH) ? km0 : k1m0;
            const long pn0 = (c2 < L_NCH) ? kn0 : k1n0;
            const int pk0  = ((c2 < L_NCH) ? c2 : c2 - L_NCH) << 6;
            const uint32_t nbase = sb + (uint32_t)((q + 2) % STAGES) * G_STAGE;

            #pragma unroll
            for (int ks = 0; ks < 4; ++ks) {
                ld_frag(sbase, ks);
                if (has_next) {
                    #pragma unroll
                    for (int p = 0; p < 3; ++p)
                        load_part(pm0, pn0, pk0, nbase, ks * 3 + p);
                }
                mma_all();
            }
            if (has_next) cp_commit();
        }

        // epilogue for tile k (registers only — overlaps in-flight loads)
        #pragma unroll
        for (int nf = 0; nf < 8; ++nf) {
            const long col = kn0 + wn + nf * 8 + 2 * tig;
            const float b0 = bias[col], b1 = bias[col + 1];
            #pragma unroll
            for (int mf = 0; mf < 4; ++mf) {
                const long r0 = km0 + wm + mf * 16 + grpl;
                *reinterpret_cast<float2*>(Cf + r0 * (long)ldc + col) =
                    make_float2(acc[mf][nf][0] + b0, acc[mf][nf][1] + b1);
                *reinterpret_cast<float2*>(Cf + (r0 + 8) * (long)ldc + col) =
                    make_float2(acc[mf][nf][2] + b0, acc[mf][nf][3] + b1);
                acc[mf][nf][0] = 0.f; acc[mf][nf][1] = 0.f;
                acc[mf][nf][2] = 0.f; acc[mf][nf][3] = 0.f;
            }
        }
        km0 = k1m0; kn0 = k1n0;
    }
}

// ---------------------------------------------------------------------------
// Launch
// ---------------------------------------------------------------------------
extern "C" void kernel_launch(void* const* d_in, const int* in_sizes, int n_in,
                              void* d_out, int out_size)
{
    const int*   ids   = (const int*)  d_in[0];
    const float* table = (const float*)d_in[1];
    const float* en_g  = (const float*)d_in[2];
    const float* en_b  = (const float*)d_in[3];
    const float* Wb    = (const float*)d_in[4];
    const float* bb    = (const float*)d_in[5];
    const float* cn_g  = (const float*)d_in[6];
    const float* cn_b  = (const float*)d_in[7];
    const float* tn_g  = (const float*)d_in[8];
    const float* tn_b  = (const float*)d_in[9];
    const float* out_W = (const float*)d_in[10];
    const float* out_b = (const float*)d_in[11];
    float* logits = (float*)d_out;

    __half *xh, *yh, *wh, *owh, *h2h;
    cudaGetSymbolAddress((void**)&xh,  g_xh);
    cudaGetSymbolAddress((void**)&yh,  g_yh);
    cudaGetSymbolAddress((void**)&wh,  g_wh);
    cudaGetSymbolAddress((void**)&owh, g_owh);
    cudaGetSymbolAddress((void**)&h2h, g_h2h);

    cudaFuncSetAttribute((const void*)gemm_f16<true, true>,
                         cudaFuncAttributeMaxDynamicSharedMemorySize, G_SMEM);
    cudaFuncSetAttribute((const void*)gemm_logits_persist,
                         cudaFuncAttributeMaxDynamicSharedMemorySize, G_SMEM);

    // 1) weights -> fp16 (single fused launch)
    conv_weights<<<(W4 + OW4 + 255) / 256, 256>>>(
        (const float4*)Wb, (const float4*)out_W, (uint2*)wh, (uint2*)owh);

    // 2) embedding + LN
    embed_ln_kernel<<<NTOK, 128>>>(ids, table, en_g, en_b);

    // 3) three residual blocks (single-term fp16 FNN, fp16 h2)
    const dim3 fnn_grid(H / BN, NTOK / BM);           // (4, 32) = 128 CTAs
    for (int bi = 0; bi < 3; ++bi) {
        const __half* W0 = wh + (long)(bi * 2 + 0) * H * H;
        const __half* W1 = wh + (long)(bi * 2 + 1) * H * H;
        const float* b0 = bb + (bi * 2 + 0) * H;
        const float* b1 = bb + (bi * 2 + 1) * H;

        gemm_f16<true, true><<<fnn_grid, 256, G_SMEM>>>(
            xh, H, W0, H, b0, (float*)nullptr, yh, H, H);
        gemm_f16<true, true><<<fnn_grid, 256, G_SMEM>>>(
            yh, H, W1, H, b1, (float*)nullptr, h2h, H, H);
        resid_ln_kernel<<<NTOK, 256>>>(cn_g + bi * C, cn_b + bi * C,
                                       tn_g + bi * E, tn_b + bi * E);
    }

    // 4) logits = tok @ out_W^T + out_b  (persistent, 148 CTAs, 27-28 tiles each)
    gemm_logits_persist<<<L_GRID, 256, G_SMEM>>>(
        xh + C, H, owh, C, out_b, logits, V);
}

// round 16
// speedup vs baseline: 1.0352x; 1.0352x over previous
#include <cuda_runtime.h>
#include <cuda_fp16.h>
#include <cstdint>

// Problem constants (fixed by the dataset)
constexpr int NTOK = 4096;      // B*S = 4*1024
constexpr int E    = 512;
constexpr int C    = 512;
constexpr int H    = 1024;
constexpr int V    = 32000;
constexpr float EPS = 1e-5f;

constexpr int W_ELEMS  = 3 * 2 * H * H;
constexpr int OW_ELEMS = V * C;
constexpr int W4  = W_ELEMS / 4;
constexpr int OW4 = OW_ELEMS / 4;

// Tiling: 128x256x64, 256 threads (8 warps, 2Mx4N), warp tile 64x64.
// 4 pipeline stages: steady-state wait_group 2 -> two chunks of latency slack.
constexpr int BM = 128, BN = 256, BK = 64;
constexpr int A_T     = BM * BK * 2;              // 16384 B
constexpr int B_T     = BN * BK * 2;              // 32768 B
constexpr int STAGES  = 4;
constexpr int G_STAGE = A_T + B_T;                // 49152
constexpr int G_SMEM  = STAGES * G_STAGE;         // 196608

// Scratch (allocation-free rule: __device__ globals)
__device__ float g_hbuf[NTOK * H];                // fp32 residual state [ctx|tok]
__device__ __half g_h2h[NTOK * H];                // fp16 FNN block output
__device__ __half g_xh[NTOK * H];                 // x fp16 (GEMM-1 in; xh[:,C:] = logits A)
__device__ __half g_yh[NTOK * H];                 // GEMM-2 input fp16
__device__ __half g_wh[W_ELEMS];                  // FNN weights fp16
__device__ __half g_owh[OW_ELEMS];                // out_W fp16

// ---------------------------------------------------------------------------
// PTX helpers
// ---------------------------------------------------------------------------
__device__ __forceinline__ uint32_t cvta_smem(const void* p) {
    uint32_t a;
    asm("{\n\t.reg .u64 t;\n\tcvta.to.shared.u64 t, %1;\n\tcvt.u32.u64 %0, t;\n\t}"
        : "=r"(a) : "l"(p));
    return a;
}
__device__ __forceinline__ uint32_t swz(uint32_t o) { return o ^ ((o >> 3) & 0x70); }

__device__ __forceinline__ void cp16(uint32_t dst, const void* src) {
    asm volatile("cp.async.cg.shared.global [%0], [%1], 16;" :: "r"(dst), "l"(src));
}
__device__ __forceinline__ void cp_commit() {
    asm volatile("cp.async.commit_group;" ::: "memory");
}

__device__ __forceinline__ void ldsm4(uint32_t* r, uint32_t addr) {
    asm volatile("ldmatrix.sync.aligned.m8n8.x4.shared.b16 {%0,%1,%2,%3}, [%4];"
                 : "=r"(r[0]), "=r"(r[1]), "=r"(r[2]), "=r"(r[3]) : "r"(addr));
}

__device__ __forceinline__ void mma16816h(float* d, const uint32_t* a,
                                          uint32_t b0, uint32_t b1) {
    asm("mma.sync.aligned.m16n8k16.row.col.f32.f16.f16.f32 "
        "{%0,%1,%2,%3}, {%4,%5,%6,%7}, {%8,%9}, {%0,%1,%2,%3};"
        : "+f"(d[0]), "+f"(d[1]), "+f"(d[2]), "+f"(d[3])
        : "r"(a[0]), "r"(a[1]), "r"(a[2]), "r"(a[3]), "r"(b0), "r"(b1));
}

__device__ __forceinline__ uint32_t pack_h2(float a, float b) {
    return (uint32_t)__half_as_ushort(__float2half_rn(a)) |
           ((uint32_t)__half_as_ushort(__float2half_rn(b)) << 16);
}

// ---------------------------------------------------------------------------
// fp32 -> fp16: both weight arrays in ONE launch
// ---------------------------------------------------------------------------
__global__ void __launch_bounds__(256) conv_weights(
    const float4* __restrict__ Wb, const float4* __restrict__ oW,
    uint2* __restrict__ wh, uint2* __restrict__ owh)
{
    const int i = blockIdx.x * 256 + threadIdx.x;
    if (i < W4) {
        const float4 x = Wb[i];
        wh[i] = make_uint2(pack_h2(x.x, x.y), pack_h2(x.z, x.w));
    } else if (i < W4 + OW4) {
        const float4 x = oW[i - W4];
        owh[i - W4] = make_uint2(pack_h2(x.x, x.y), pack_h2(x.z, x.w));
    }
}

// ---------------------------------------------------------------------------
// 128-thread-group reduction (two groups per 256-thread block)
// ---------------------------------------------------------------------------
__device__ __forceinline__ void group_reduce_2(float& s, float& s2,
                                               int grp, int wig) {
    #pragma unroll
    for (int o = 16; o > 0; o >>= 1) {
        s  += __shfl_xor_sync(0xFFFFFFFFu, s,  o);
        s2 += __shfl_xor_sync(0xFFFFFFFFu, s2, o);
    }
    __shared__ float red[2][8];
    int lid = threadIdx.x & 31;
    if (lid == 0) { red[grp][wig] = s; red[grp][4 + wig] = s2; }
    __syncthreads();
    s  = red[grp][0] + red[grp][1] + red[grp][2] + red[grp][3];
    s2 = red[grp][4] + red[grp][5] + red[grp][6] + red[grp][7];
}

// ---------------------------------------------------------------------------
// Embedding gather + LN -> hbuf fp32 [0|tok] and x fp16 (full row)
// ---------------------------------------------------------------------------
__global__ void __launch_bounds__(128) embed_ln_kernel(
    const int* __restrict__ ids, const float* __restrict__ table,
    const float* __restrict__ g, const float* __restrict__ b)
{
    const int tok = blockIdx.x;
    const int tid = threadIdx.x;
    const long id = ids[tok];

    float4 x = reinterpret_cast<const float4*>(table + id * (long)E)[tid];
    float s  = x.x + x.y + x.z + x.w;
    float s2 = x.x * x.x + x.y * x.y + x.z * x.z + x.w * x.w;
    #pragma unroll
    for (int o = 16; o > 0; o >>= 1) {
        s  += __shfl_xor_sync(0xFFFFFFFFu, s,  o);
        s2 += __shfl_xor_sync(0xFFFFFFFFu, s2, o);
    }
    __shared__ float red[8];
    int wid = tid >> 5, lid = tid & 31;
    if (lid == 0) { red[wid] = s; red[4 + wid] = s2; }
    __syncthreads();
    s  = red[0] + red[1] + red[2] + red[3];
    s2 = red[4] + red[5] + red[6] + red[7];

    const float mean = s * (1.0f / E);
    const float var  = s2 * (1.0f / E) - mean * mean;
    const float rstd = rsqrtf(var + EPS);

    float4 gg = reinterpret_cast<const float4*>(g)[tid];
    float4 bb = reinterpret_cast<const float4*>(b)[tid];
    float4 y;
    y.x = (x.x - mean) * rstd * gg.x + bb.x;
    y.y = (x.y - mean) * rstd * gg.y + bb.y;
    y.z = (x.z - mean) * rstd * gg.z + bb.z;
    y.w = (x.w - mean) * rstd * gg.w + bb.w;

    const long rbase = (long)tok * H;
    float* row = g_hbuf + rbase;
    reinterpret_cast<float4*>(row + C)[tid] = y;
    reinterpret_cast<float4*>(row)[tid] = make_float4(0.f, 0.f, 0.f, 0.f);

    reinterpret_cast<uint2*>(g_xh + rbase + C)[tid] =
        make_uint2(pack_h2(y.x, y.y), pack_h2(y.z, y.w));
    reinterpret_cast<uint2*>(g_xh + rbase)[tid] = make_uint2(0, 0);
}

// ---------------------------------------------------------------------------
// Residual + LN, BOTH halves in one 256-thread block (grp 0 = ctx, 1 = tok).
// Reads h2 in fp16; writes hbuf fp32 and x fp16.
// ---------------------------------------------------------------------------
__global__ void __launch_bounds__(256) resid_ln_kernel(
    const float* __restrict__ cg, const float* __restrict__ cb,
    const float* __restrict__ tg, const float* __restrict__ tb)
{
    const int tok = blockIdx.x;
    const int grp = threadIdx.x >> 7;
    const int t   = threadIdx.x & 127;
    const int wig = (threadIdx.x >> 5) & 3;
    const float* g  = grp ? tg : cg;
    const float* bp = grp ? tb : cb;

    const long base = (long)tok * H + grp * C;
    float4 a = reinterpret_cast<const float4*>(g_hbuf + base)[t];
    uint2 hp = reinterpret_cast<const uint2*>(g_h2h + base)[t];
    float2 h0 = __half22float2(*reinterpret_cast<__half2*>(&hp.x));
    float2 h1 = __half22float2(*reinterpret_cast<__half2*>(&hp.y));
    float4 x;
    x.x = a.x + h0.x; x.y = a.y + h0.y; x.z = a.z + h1.x; x.w = a.w + h1.y;

    float s  = x.x + x.y + x.z + x.w;
    float s2 = x.x * x.x + x.y * x.y + x.z * x.z + x.w * x.w;
    group_reduce_2(s, s2, grp, wig);

    const float mean = s * (1.0f / C);
    const float var  = s2 * (1.0f / C) - mean * mean;
    const float rstd = rsqrtf(var + EPS);

    float4 gg = reinterpret_cast<const float4*>(g)[t];
    float4 bb = reinterpret_cast<const float4*>(bp)[t];
    float4 y;
    y.x = (x.x - mean) * rstd * gg.x + bb.x;
    y.y = (x.y - mean) * rstd * gg.y + bb.y;
    y.z = (x.z - mean) * rstd * gg.z + bb.z;
    y.w = (x.w - mean) * rstd * gg.w + bb.w;
    reinterpret_cast<float4*>(g_hbuf + base)[t] = y;

    reinterpret_cast<uint2*>(g_xh + base)[t] =
        make_uint2(pack_h2(y.x, y.y), pack_h2(y.z, y.w));
}

// ---------------------------------------------------------------------------
// Unified single-term fp16 GEMM: D = A @ B^T + bias, fp32 accumulate.
// 128x256 tile, warp 64x64. 4-stage cp.async pipeline (wait_group 2 steady
// state -> two chunks of latency slack), SW128 swizzle.
// ---------------------------------------------------------------------------
template <bool RELU, bool OUT16>
__global__ void __launch_bounds__(256, 1) gemm_f16(
    const __half* __restrict__ A, int lda,
    const __half* __restrict__ B, int ldb,
    const float* __restrict__ bias,
    float* __restrict__ Cf, __half* __restrict__ Ch,
    int ldc, int K)
{
    extern __shared__ char smem[];
    const uint32_t sb = cvta_smem(smem);
    const int tid = threadIdx.x;
    const int w   = tid >> 5;
    const int l   = tid & 31;
    const int wm  = (w >> 2) * 64;
    const int wn  = (w & 3) * 64;
    const long m0 = (long)blockIdx.y * BM;
    const long n0 = (long)blockIdx.x * BN;

    const int lrow  = ((l >> 3) & 1) * 8 + (l & 7);
    const int lkseg = ((l >> 4) & 1) * 16;

    const int NC = K >> 6;   // >= 8 for all our shapes

    const int ldr  = tid >> 3;
    const int ldc8 = (tid & 7) * 8;
    const uint32_t lso = (uint32_t)((tid & 7) * 16);

    auto load_part = [&](int c, uint32_t sbase, int it) {
        const int k0 = c << 6;
        const int r = it * 32 + ldr;
        if (r < BM) {
            cp16(sbase + swz((uint32_t)(r * 128) + lso),
                 A + (m0 + r) * (long)lda + k0 + ldc8);
        } else {
            cp16(sbase + A_T + swz((uint32_t)((r - BM) * 128) + lso),
                 B + (n0 + r - BM) * (long)ldb + k0 + ldc8);
        }
    };
    auto load_chunk = [&](int c, int stage) {
        const uint32_t sbase = sb + (uint32_t)stage * G_STAGE;
        #pragma unroll
        for (int it = 0; it < 12; ++it) load_part(c, sbase, it);
    };

    float acc[4][8][4];
    #pragma unroll
    for (int i = 0; i < 4; ++i)
        #pragma unroll
        for (int j = 0; j < 8; ++j)
            #pragma unroll
            for (int q = 0; q < 4; ++q) acc[i][j][q] = 0.0f;

    uint32_t Af[4][4], Bf[4][4];

    auto ld_frag = [&](uint32_t sbase, int ks) {
        const int kb = ks * 32 + lkseg;
        #pragma unroll
        for (int mf = 0; mf < 4; ++mf) {
            const uint32_t off = swz((uint32_t)((wm + mf * 16 + lrow) * 128 + kb));
            ldsm4(Af[mf], sbase + off);
        }
        #pragma unroll
        for (int nf2 = 0; nf2 < 4; ++nf2) {
            const uint32_t off = swz((uint32_t)((wn + nf2 * 16 + lrow) * 128 + kb));
            ldsm4(Bf[nf2], sbase + A_T + off);
        }
    };
    auto mma_all = [&]() {
        #pragma unroll
        for (int mf = 0; mf < 4; ++mf)
            #pragma unroll
            for (int nf = 0; nf < 8; ++nf) {
                const int p = nf >> 1, q = nf & 1;
                mma16816h(acc[mf][nf], Af[mf], Bf[p][q], Bf[p][q + 2]);
            }
    };

    // prologue: 3 chunks in flight (NC >= 8 always here)
    load_chunk(0, 0); cp_commit();
    load_chunk(1, 1); cp_commit();
    load_chunk(2, 2); cp_commit();

    for (int c = 0; c < NC; ++c) {
        if (c + 3 <= NC - 1)      asm volatile("cp.async.wait_group 2;" ::: "memory");
        else if (c + 2 <= NC - 1) asm volatile("cp.async.wait_group 1;" ::: "memory");
        else                      asm volatile("cp.async.wait_group 0;" ::: "memory");
        __syncthreads();

        const uint32_t sbase = sb + (uint32_t)(c % STAGES) * G_STAGE;
        const int cn = c + 3;
        const uint32_t nbase = sb + (uint32_t)(cn % STAGES) * G_STAGE;
        const bool has_next = cn < NC;
        // stage-reuse safety: chunk c+3 writes stage (c+3)%4 == (c-1)%4,
        // last read in iteration c-1; the barrier above (iteration c) proves
        // all warps have left it.

        #pragma unroll
        for (int ks = 0; ks < 4; ++ks) {
            ld_frag(sbase, ks);
            if (has_next) {
                #pragma unroll
                for (int p = 0; p < 3; ++p) load_part(cn, nbase, ks * 3 + p);
            }
            mma_all();
        }
        if (has_next) cp_commit();
    }

    const int tig = l & 3, grp = l >> 2;
    #pragma unroll
    for (int nf = 0; nf < 8; ++nf) {
        const long col = n0 + wn + nf * 8 + 2 * tig;
        const float b0 = bias[col], b1 = bias[col + 1];
        #pragma unroll
        for (int mf = 0; mf < 4; ++mf) {
            const long r0 = m0 + wm + mf * 16 + grp;
            float v00 = acc[mf][nf][0] + b0, v01 = acc[mf][nf][1] + b1;
            float v10 = acc[mf][nf][2] + b0, v11 = acc[mf][nf][3] + b1;
            if (RELU) {
                v00 = fmaxf(v00, 0.f); v01 = fmaxf(v01, 0.f);
                v10 = fmaxf(v10, 0.f); v11 = fmaxf(v11, 0.f);
            }
            if (OUT16) {
                *reinterpret_cast<uint32_t*>(Ch + r0 * (long)ldc + col) = pack_h2(v00, v01);
                *reinterpret_cast<uint32_t*>(Ch + (r0 + 8) * (long)ldc + col) = pack_h2(v10, v11);
            } else {
                *reinterpret_cast<float2*>(Cf + r0 * (long)ldc + col) = make_float2(v00, v01);
                *reinterpret_cast<float2*>(Cf + (r0 + 8) * (long)ldc + col) = make_float2(v10, v11);
            }
        }
    }
}

// ---------------------------------------------------------------------------
// Launch
// ---------------------------------------------------------------------------
extern "C" void kernel_launch(void* const* d_in, const int* in_sizes, int n_in,
                              void* d_out, int out_size)
{
    const int*   ids   = (const int*)  d_in[0];
    const float* table = (const float*)d_in[1];
    const float* en_g  = (const float*)d_in[2];
    const float* en_b  = (const float*)d_in[3];
    const float* Wb    = (const float*)d_in[4];
    const float* bb    = (const float*)d_in[5];
    const float* cn_g  = (const float*)d_in[6];
    const float* cn_b  = (const float*)d_in[7];
    const float* tn_g  = (const float*)d_in[8];
    const float* tn_b  = (const float*)d_in[9];
    const float* out_W = (const float*)d_in[10];
    const float* out_b = (const float*)d_in[11];
    float* logits = (float*)d_out;

    __half *xh, *yh, *wh, *owh, *h2h;
    cudaGetSymbolAddress((void**)&xh,  g_xh);
    cudaGetSymbolAddress((void**)&yh,  g_yh);
    cudaGetSymbolAddress((void**)&wh,  g_wh);
    cudaGetSymbolAddress((void**)&owh, g_owh);
    cudaGetSymbolAddress((void**)&h2h, g_h2h);

    cudaFuncSetAttribute((const void*)gemm_f16<true, true>,
                         cudaFuncAttributeMaxDynamicSharedMemorySize, G_SMEM);
    cudaFuncSetAttribute((const void*)gemm_f16<false, false>,
                         cudaFuncAttributeMaxDynamicSharedMemorySize, G_SMEM);

    // 1) weights -> fp16 (single fused launch)
    conv_weights<<<(W4 + OW4 + 255) / 256, 256>>>(
        (const float4*)Wb, (const float4*)out_W, (uint2*)wh, (uint2*)owh);

    // 2) embedding + LN
    embed_ln_kernel<<<NTOK, 128>>>(ids, table, en_g, en_b);

    // 3) three residual blocks (single-term fp16 FNN, fp16 h2)
    const dim3 fnn_grid(H / BN, NTOK / BM);           // (4, 32) = 128 CTAs
    for (int bi = 0; bi < 3; ++bi) {
        const __half* W0 = wh + (long)(bi * 2 + 0) * H * H;
        const __half* W1 = wh + (long)(bi * 2 + 1) * H * H;
        const float* b0 = bb + (bi * 2 + 0) * H;
        const float* b1 = bb + (bi * 2 + 1) * H;

        gemm_f16<true, true><<<fnn_grid, 256, G_SMEM>>>(
            xh, H, W0, H, b0, (float*)nullptr, yh, H, H);
        gemm_f16<true, true><<<fnn_grid, 256, G_SMEM>>>(
            yh, H, W1, H, b1, (float*)nullptr, h2h, H, H);
        resid_ln_kernel<<<NTOK, 256>>>(cn_g + bi * C, cn_b + bi * C,
                                       tn_g + bi * E, tn_b + bi * E);
    }

    // 4) logits = tok @ out_W^T + out_b  (A = xh[:, C:] fp16, fp32 acc)
    const dim3 out_grid(V / BN, NTOK / BM);           // (125, 32)
    gemm_f16<false, false><<<out_grid, 256, G_SMEM>>>(
        xh + C, H, owh, C, out_b, logits, (__half*)nullptr, V, C);
}

// round 17
// speedup vs baseline: 1.0689x; 1.0325x over previous
#include <cuda_runtime.h>
#include <cuda_fp16.h>
#include <cstdint>

// Problem constants (fixed by the dataset)
constexpr int NTOK = 4096;      // B*S = 4*1024
constexpr int E    = 512;
constexpr int C    = 512;
constexpr int H    = 1024;
constexpr int V    = 32000;
constexpr float EPS = 1e-5f;

constexpr int W_ELEMS  = 3 * 2 * H * H;
constexpr int OW_ELEMS = V * C;
constexpr int W4  = W_ELEMS / 4;
constexpr int OW4 = OW_ELEMS / 4;

// Tiling: 128x256x64, 256 threads (8 warps, 2Mx4N), warp tile 64x64.
// 3 pipeline stages (R14 best config).
constexpr int BM = 128, BN = 256, BK = 64;
constexpr int A_T     = BM * BK * 2;              // 16384 B
constexpr int B_T     = BN * BK * 2;              // 32768 B
constexpr int STAGES  = 3;
constexpr int G_STAGE = A_T + B_T;                // 49152
constexpr int G_SMEM  = STAGES * G_STAGE;         // 147456

// Scratch (allocation-free rule: __device__ globals)
__device__ float g_hbuf[NTOK * H];                // fp32 residual state [ctx|tok]
__device__ __half g_h2h[NTOK * H];                // fp16 FNN block output
__device__ __half g_xh[NTOK * H];                 // x fp16 (GEMM-1 in; xh[:,C:] = logits A)
__device__ __half g_yh[NTOK * H];                 // GEMM-2 input fp16
__device__ __half g_wh[W_ELEMS];                  // FNN weights fp16
__device__ __half g_owh[OW_ELEMS];                // out_W fp16

// ---------------------------------------------------------------------------
// PTX helpers
// ---------------------------------------------------------------------------
__device__ __forceinline__ uint32_t cvta_smem(const void* p) {
    uint32_t a;
    asm("{\n\t.reg .u64 t;\n\tcvta.to.shared.u64 t, %1;\n\tcvt.u32.u64 %0, t;\n\t}"
        : "=r"(a) : "l"(p));
    return a;
}
__device__ __forceinline__ uint32_t swz(uint32_t o) { return o ^ ((o >> 3) & 0x70); }

__device__ __forceinline__ void cp16(uint32_t dst, const void* src) {
    asm volatile("cp.async.cg.shared.global [%0], [%1], 16;" :: "r"(dst), "l"(src));
}
__device__ __forceinline__ void cp_commit() {
    asm volatile("cp.async.commit_group;" ::: "memory");
}

__device__ __forceinline__ void ldsm4(uint32_t* r, uint32_t addr) {
    asm volatile("ldmatrix.sync.aligned.m8n8.x4.shared.b16 {%0,%1,%2,%3}, [%4];"
                 : "=r"(r[0]), "=r"(r[1]), "=r"(r[2]), "=r"(r[3]) : "r"(addr));
}

__device__ __forceinline__ void mma16816h(float* d, const uint32_t* a,
                                          uint32_t b0, uint32_t b1) {
    asm("mma.sync.aligned.m16n8k16.row.col.f32.f16.f16.f32 "
        "{%0,%1,%2,%3}, {%4,%5,%6,%7}, {%8,%9}, {%0,%1,%2,%3};"
        : "+f"(d[0]), "+f"(d[1]), "+f"(d[2]), "+f"(d[3])
        : "r"(a[0]), "r"(a[1]), "r"(a[2]), "r"(a[3]), "r"(b0), "r"(b1));
}

__device__ __forceinline__ uint32_t pack_h2(float a, float b) {
    return (uint32_t)__half_as_ushort(__float2half_rn(a)) |
           ((uint32_t)__half_as_ushort(__float2half_rn(b)) << 16);
}

// ---------------------------------------------------------------------------
// fp32 -> fp16: both weight arrays in ONE launch
// ---------------------------------------------------------------------------
__global__ void __launch_bounds__(256) conv_weights(
    const float4* __restrict__ Wb, const float4* __restrict__ oW,
    uint2* __restrict__ wh, uint2* __restrict__ owh)
{
    const int i = blockIdx.x * 256 + threadIdx.x;
    if (i < W4) {
        const float4 x = Wb[i];
        wh[i] = make_uint2(pack_h2(x.x, x.y), pack_h2(x.z, x.w));
    } else if (i < W4 + OW4) {
        const float4 x = oW[i - W4];
        owh[i - W4] = make_uint2(pack_h2(x.x, x.y), pack_h2(x.z, x.w));
    }
}

// ---------------------------------------------------------------------------
// 128-thread-group reduction (two groups per 256-thread block)
// ---------------------------------------------------------------------------
__device__ __forceinline__ void group_reduce_2(float& s, float& s2,
                                               int grp, int wig) {
    #pragma unroll
    for (int o = 16; o > 0; o >>= 1) {
        s  += __shfl_xor_sync(0xFFFFFFFFu, s,  o);
        s2 += __shfl_xor_sync(0xFFFFFFFFu, s2, o);
    }
    __shared__ float red[2][8];
    int lid = threadIdx.x & 31;
    if (lid == 0) { red[grp][wig] = s; red[grp][4 + wig] = s2; }
    __syncthreads();
    s  = red[grp][0] + red[grp][1] + red[grp][2] + red[grp][3];
    s2 = red[grp][4] + red[grp][5] + red[grp][6] + red[grp][7];
}

// ---------------------------------------------------------------------------
// Embedding gather + LN -> hbuf fp32 [0|tok] and x fp16 (full row)
// ---------------------------------------------------------------------------
__global__ void __launch_bounds__(128) embed_ln_kernel(
    const int* __restrict__ ids, const float* __restrict__ table,
    const float* __restrict__ g, const float* __restrict__ b)
{
    const int tok = blockIdx.x;
    const int tid = threadIdx.x;
    const long id = ids[tok];

    float4 x = reinterpret_cast<const float4*>(table + id * (long)E)[tid];
    float s  = x.x + x.y + x.z + x.w;
    float s2 = x.x * x.x + x.y * x.y + x.z * x.z + x.w * x.w;
    #pragma unroll
    for (int o = 16; o > 0; o >>= 1) {
        s  += __shfl_xor_sync(0xFFFFFFFFu, s,  o);
        s2 += __shfl_xor_sync(0xFFFFFFFFu, s2, o);
    }
    __shared__ float red[8];
    int wid = tid >> 5, lid = tid & 31;
    if (lid == 0) { red[wid] = s; red[4 + wid] = s2; }
    __syncthreads();
    s  = red[0] + red[1] + red[2] + red[3];
    s2 = red[4] + red[5] + red[6] + red[7];

    const float mean = s * (1.0f / E);
    const float var  = s2 * (1.0f / E) - mean * mean;
    const float rstd = rsqrtf(var + EPS);

    float4 gg = reinterpret_cast<const float4*>(g)[tid];
    float4 bb = reinterpret_cast<const float4*>(b)[tid];
    float4 y;
    y.x = (x.x - mean) * rstd * gg.x + bb.x;
    y.y = (x.y - mean) * rstd * gg.y + bb.y;
    y.z = (x.z - mean) * rstd * gg.z + bb.z;
    y.w = (x.w - mean) * rstd * gg.w + bb.w;

    const long rbase = (long)tok * H;
    float* row = g_hbuf + rbase;
    reinterpret_cast<float4*>(row + C)[tid] = y;
    reinterpret_cast<float4*>(row)[tid] = make_float4(0.f, 0.f, 0.f, 0.f);

    reinterpret_cast<uint2*>(g_xh + rbase + C)[tid] =
        make_uint2(pack_h2(y.x, y.y), pack_h2(y.z, y.w));
    reinterpret_cast<uint2*>(g_xh + rbase)[tid] = make_uint2(0, 0);
}

// ---------------------------------------------------------------------------
// Residual + LN, BOTH halves in one 256-thread block (grp 0 = ctx, 1 = tok).
// Reads h2 in fp16; writes hbuf fp32 and x fp16.
// ---------------------------------------------------------------------------
__global__ void __launch_bounds__(256) resid_ln_kernel(
    const float* __restrict__ cg, const float* __restrict__ cb,
    const float* __restrict__ tg, const float* __restrict__ tb)
{
    const int tok = blockIdx.x;
    const int grp = threadIdx.x >> 7;
    const int t   = threadIdx.x & 127;
    const int wig = (threadIdx.x >> 5) & 3;
    const float* g  = grp ? tg : cg;
    const float* bp = grp ? tb : cb;

    const long base = (long)tok * H + grp * C;
    float4 a = reinterpret_cast<const float4*>(g_hbuf + base)[t];
    uint2 hp = reinterpret_cast<const uint2*>(g_h2h + base)[t];
    float2 h0 = __half22float2(*reinterpret_cast<__half2*>(&hp.x));
    float2 h1 = __half22float2(*reinterpret_cast<__half2*>(&hp.y));
    float4 x;
    x.x = a.x + h0.x; x.y = a.y + h0.y; x.z = a.z + h1.x; x.w = a.w + h1.y;

    float s  = x.x + x.y + x.z + x.w;
    float s2 = x.x * x.x + x.y * x.y + x.z * x.z + x.w * x.w;
    group_reduce_2(s, s2, grp, wig);

    const float mean = s * (1.0f / C);
    const float var  = s2 * (1.0f / C) - mean * mean;
    const float rstd = rsqrtf(var + EPS);

    float4 gg = reinterpret_cast<const float4*>(g)[t];
    float4 bb = reinterpret_cast<const float4*>(bp)[t];
    float4 y;
    y.x = (x.x - mean) * rstd * gg.x + bb.x;
    y.y = (x.y - mean) * rstd * gg.y + bb.y;
    y.z = (x.z - mean) * rstd * gg.z + bb.z;
    y.w = (x.w - mean) * rstd * gg.w + bb.w;
    reinterpret_cast<float4*>(g_hbuf + base)[t] = y;

    reinterpret_cast<uint2*>(g_xh + base)[t] =
        make_uint2(pack_h2(y.x, y.y), pack_h2(y.z, y.w));
}

// ---------------------------------------------------------------------------
// Unified single-term fp16 GEMM: D = A @ B^T + bias, fp32 accumulate.
// 128x256 tile, warp 64x64. 3-stage cp.async pipeline, SW128 swizzle.
// (R14 config — measured best; at the legacy-HMMA dispatch floor.)
// ---------------------------------------------------------------------------
template <bool RELU, bool OUT16>
__global__ void __launch_bounds__(256, 1) gemm_f16(
    const __half* __restrict__ A, int lda,
    const __half* __restrict__ B, int ldb,
    const float* __restrict__ bias,
    float* __restrict__ Cf, __half* __restrict__ Ch,
    int ldc, int K)
{
    extern __shared__ char smem[];
    const uint32_t sb = cvta_smem(smem);
    const int tid = threadIdx.x;
    const int w   = tid >> 5;
    const int l   = tid & 31;
    const int wm  = (w >> 2) * 64;
    const int wn  = (w & 3) * 64;
    const long m0 = (long)blockIdx.y * BM;
    const long n0 = (long)blockIdx.x * BN;

    const int lrow  = ((l >> 3) & 1) * 8 + (l & 7);
    const int lkseg = ((l >> 4) & 1) * 16;

    const int NC = K >> 6;

    const int ldr  = tid >> 3;
    const int ldc8 = (tid & 7) * 8;
    const uint32_t lso = (uint32_t)((tid & 7) * 16);

    auto load_part = [&](int c, uint32_t sbase, int it) {
        const int k0 = c << 6;
        const int r = it * 32 + ldr;
        if (r < BM) {
            cp16(sbase + swz((uint32_t)(r * 128) + lso),
                 A + (m0 + r) * (long)lda + k0 + ldc8);
        } else {
            cp16(sbase + A_T + swz((uint32_t)((r - BM) * 128) + lso),
                 B + (n0 + r - BM) * (long)ldb + k0 + ldc8);
        }
    };
    auto load_chunk = [&](int c, int stage) {
        const uint32_t sbase = sb + (uint32_t)stage * G_STAGE;
        #pragma unroll
        for (int it = 0; it < 12; ++it) load_part(c, sbase, it);
    };

    float acc[4][8][4];
    #pragma unroll
    for (int i = 0; i < 4; ++i)
        #pragma unroll
        for (int j = 0; j < 8; ++j)
            #pragma unroll
            for (int q = 0; q < 4; ++q) acc[i][j][q] = 0.0f;

    uint32_t Af[4][4], Bf[4][4];

    auto ld_frag = [&](uint32_t sbase, int ks) {
        const int kb = ks * 32 + lkseg;
        #pragma unroll
        for (int mf = 0; mf < 4; ++mf) {
            const uint32_t off = swz((uint32_t)((wm + mf * 16 + lrow) * 128 + kb));
            ldsm4(Af[mf], sbase + off);
        }
        #pragma unroll
        for (int nf2 = 0; nf2 < 4; ++nf2) {
            const uint32_t off = swz((uint32_t)((wn + nf2 * 16 + lrow) * 128 + kb));
            ldsm4(Bf[nf2], sbase + A_T + off);
        }
    };
    auto mma_all = [&]() {
        #pragma unroll
        for (int mf = 0; mf < 4; ++mf)
            #pragma unroll
            for (int nf = 0; nf < 8; ++nf) {
                const int p = nf >> 1, q = nf & 1;
                mma16816h(acc[mf][nf], Af[mf], Bf[p][q], Bf[p][q + 2]);
            }
    };

    load_chunk(0, 0); cp_commit();
    if (NC > 1) { load_chunk(1, 1); cp_commit(); }

    for (int c = 0; c < NC; ++c) {
        if (c + 1 < NC) asm volatile("cp.async.wait_group 1;" ::: "memory");
        else            asm volatile("cp.async.wait_group 0;" ::: "memory");
        __syncthreads();

        const uint32_t sbase = sb + (uint32_t)(c % STAGES) * G_STAGE;
        const int cn = c + 2;
        const uint32_t nbase = sb + (uint32_t)(cn % STAGES) * G_STAGE;
        const bool has_next = cn < NC;

        #pragma unroll
        for (int ks = 0; ks < 4; ++ks) {
            ld_frag(sbase, ks);
            if (has_next) {
                #pragma unroll
                for (int p = 0; p < 3; ++p) load_part(cn, nbase, ks * 3 + p);
            }
            mma_all();
        }
        if (has_next) cp_commit();
    }

    const int tig = l & 3, grp = l >> 2;
    #pragma unroll
    for (int nf = 0; nf < 8; ++nf) {
        const long col = n0 + wn + nf * 8 + 2 * tig;
        const float b0 = bias[col], b1 = bias[col + 1];
        #pragma unroll
        for (int mf = 0; mf < 4; ++mf) {
            const long r0 = m0 + wm + mf * 16 + grp;
            float v00 = acc[mf][nf][0] + b0, v01 = acc[mf][nf][1] + b1;
            float v10 = acc[mf][nf][2] + b0, v11 = acc[mf][nf][3] + b1;
            if (RELU) {
                v00 = fmaxf(v00, 0.f); v01 = fmaxf(v01, 0.f);
                v10 = fmaxf(v10, 0.f); v11 = fmaxf(v11, 0.f);
            }
            if (OUT16) {
                *reinterpret_cast<uint32_t*>(Ch + r0 * (long)ldc + col) = pack_h2(v00, v01);
                *reinterpret_cast<uint32_t*>(Ch + (r0 + 8) * (long)ldc + col) = pack_h2(v10, v11);
            } else {
                *reinterpret_cast<float2*>(Cf + r0 * (long)ldc + col) = make_float2(v00, v01);
                *reinterpret_cast<float2*>(Cf + (r0 + 8) * (long)ldc + col) = make_float2(v10, v11);
            }
        }
    }
}

// ---------------------------------------------------------------------------
// Launch
// ---------------------------------------------------------------------------
extern "C" void kernel_launch(void* const* d_in, const int* in_sizes, int n_in,
                              void* d_out, int out_size)
{
    const int*   ids   = (const int*)  d_in[0];
    const float* table = (const float*)d_in[1];
    const float* en_g  = (const float*)d_in[2];
    const float* en_b  = (const float*)d_in[3];
    const float* Wb    = (const float*)d_in[4];
    const float* bb    = (const float*)d_in[5];
    const float* cn_g  = (const float*)d_in[6];
    const float* cn_b  = (const float*)d_in[7];
    const float* tn_g  = (const float*)d_in[8];
    const float* tn_b  = (const float*)d_in[9];
    const float* out_W = (const float*)d_in[10];
    const float* out_b = (const float*)d_in[11];
    float* logits = (float*)d_out;

    __half *xh, *yh, *wh, *owh, *h2h;
    cudaGetSymbolAddress((void**)&xh,  g_xh);
    cudaGetSymbolAddress((void**)&yh,  g_yh);
    cudaGetSymbolAddress((void**)&wh,  g_wh);
    cudaGetSymbolAddress((void**)&owh, g_owh);
    cudaGetSymbolAddress((void**)&h2h, g_h2h);

    cudaFuncSetAttribute((const void*)gemm_f16<true, true>,
                         cudaFuncAttributeMaxDynamicSharedMemorySize, G_SMEM);
    cudaFuncSetAttribute((const void*)gemm_f16<false, false>,
                         cudaFuncAttributeMaxDynamicSharedMemorySize, G_SMEM);

    // 1) weights -> fp16 (single fused launch)
    conv_weights<<<(W4 + OW4 + 255) / 256, 256>>>(
        (const float4*)Wb, (const float4*)out_W, (uint2*)wh, (uint2*)owh);

    // 2) embedding + LN
    embed_ln_kernel<<<NTOK, 128>>>(ids, table, en_g, en_b);

    // 3) three residual blocks (single-term fp16 FNN, fp16 h2)
    const dim3 fnn_grid(H / BN, NTOK / BM);           // (4, 32) = 128 CTAs
    for (int bi = 0; bi < 3; ++bi) {
        const __half* W0 = wh + (long)(bi * 2 + 0) * H * H;
        const __half* W1 = wh + (long)(bi * 2 + 1) * H * H;
        const float* b0 = bb + (bi * 2 + 0) * H;
        const float* b1 = bb + (bi * 2 + 1) * H;

        if (bi == 0) {
            // Block 0: ctx half of x is exactly zero -> K=512 using only the
            // tok half of A and the matching column block of W0 (bit-exact).
            gemm_f16<true, true><<<fnn_grid, 256, G_SMEM>>>(
                xh + C, H, W0 + C, H, b0, (float*)nullptr, yh, H, C);
        } else {
            gemm_f16<true, true><<<fnn_grid, 256, G_SMEM>>>(
                xh, H, W0, H, b0, (float*)nullptr, yh, H, H);
        }
        gemm_f16<true, true><<<fnn_grid, 256, G_SMEM>>>(
            yh, H, W1, H, b1, (float*)nullptr, h2h, H, H);
        resid_ln_kernel<<<NTOK, 256>>>(cn_g + bi * C, cn_b + bi * C,
                                       tn_g + bi * E, tn_b + bi * E);
    }

    // 4) logits = tok @ out_W^T + out_b  (A = xh[:, C:] fp16, fp32 acc)
    const dim3 out_grid(V / BN, NTOK / BM);           // (125, 32)
    gemm_f16<false, false><<<out_grid, 256, G_SMEM>>>(
        xh + C, H, owh, C, out_b, logits, (__half*)nullptr, V, C);
}